// round 1
// baseline (speedup 1.0000x reference)
#include <cuda_runtime.h>
#include <math.h>

#define NN 50000
#define NE 800000
#define DD 64
#define NR 500
#define NT 1000

// ---- scratch (no allocs allowed) ----
__device__ float g_ex[NE];
__device__ float g_den[NN];
__device__ float g_agg[NN * DD];
__device__ float g_hatt[NN];
__device__ float g_tatt[NN];
__device__ float g_ratt[NR];
__device__ float g_tsatt[NT];

// ---------------------------------------------------------------------------
// Zero den + agg
// ---------------------------------------------------------------------------
__global__ void k_init() {
    int i = blockIdx.x * blockDim.x + threadIdx.x;
    int stride = gridDim.x * blockDim.x;
    for (int j = i; j < NN * DD; j += stride) g_agg[j] = 0.f;
    for (int j = i; j < NN; j += stride) g_den[j] = 0.f;
}

// ---------------------------------------------------------------------------
// Per-row scalar attention projections: warp per row.
// tasks: [0,NN) nodes (h_att & t_att), [NN,NN+NR) rels, [NN+NR,NN+NR+NT) times
// ---------------------------------------------------------------------------
__global__ void k_scalar(const float* __restrict__ x,
                         const float* __restrict__ rel,
                         const float* __restrict__ tm,
                         const float* __restrict__ ah,
                         const float* __restrict__ at,
                         const float* __restrict__ ar,
                         const float* __restrict__ ats) {
    int w = (blockIdx.x * blockDim.x + threadIdx.x) >> 5;
    int lane = threadIdx.x & 31;
    if (w < NN) {
        const float* row = x + (size_t)w * DD;
        float v0 = row[lane], v1 = row[lane + 32];
        float h = v0 * ah[lane] + v1 * ah[lane + 32];
        float t = v0 * at[lane] + v1 * at[lane + 32];
#pragma unroll
        for (int o = 16; o; o >>= 1) {
            h += __shfl_xor_sync(0xffffffffu, h, o);
            t += __shfl_xor_sync(0xffffffffu, t, o);
        }
        if (lane == 0) { g_hatt[w] = h; g_tatt[w] = t; }
    } else if (w < NN + NR) {
        int r = w - NN;
        const float* row = rel + (size_t)r * DD;
        float s = row[lane] * ar[lane] + row[lane + 32] * ar[lane + 32];
#pragma unroll
        for (int o = 16; o; o >>= 1) s += __shfl_xor_sync(0xffffffffu, s, o);
        if (lane == 0) g_ratt[r] = s;
    } else if (w < NN + NR + NT) {
        int t = w - NN - NR;
        const float* row = tm + (size_t)t * DD;
        float s = row[lane] * ats[lane] + row[lane + 32] * ats[lane + 32];
#pragma unroll
        for (int o = 16; o; o >>= 1) s += __shfl_xor_sync(0xffffffffu, s, o);
        if (lane == 0) g_tsatt[t] = s;
    }
}

// ---------------------------------------------------------------------------
// Edge pass 1: ex = exp(leaky_relu(logit)); den[dst] += ex
// (softmax is shift-invariant; logits bounded well below fp32 overflow, so no
//  segment_max pass needed — ratio is mathematically identical)
// ---------------------------------------------------------------------------
__global__ void k_edge1(const int* __restrict__ src, const int* __restrict__ dst,
                        const int* __restrict__ ety, const int* __restrict__ eti) {
    int i = blockIdx.x * blockDim.x + threadIdx.x;
    if (i >= NE) return;
    int d = dst[i];
    float e = g_hatt[src[i]] - g_tatt[d] + g_ratt[ety[i]] + g_tsatt[eti[i]];
    e = (e > 0.f) ? e : 0.1f * e;
    float ex = expf(e);
    g_ex[i] = ex;
    atomicAdd(&g_den[d], ex);
}

// ---------------------------------------------------------------------------
// Edge pass 2 (dominant): 16 threads per edge, float4 per thread.
// agg[dst] += att * (x[src]+time) * (rel+time)  via red.global.add.v4.f32
// ---------------------------------------------------------------------------
__global__ void k_edge2(const float* __restrict__ x,
                        const float* __restrict__ rel,
                        const float* __restrict__ tm,
                        const int* __restrict__ src, const int* __restrict__ dst,
                        const int* __restrict__ ety, const int* __restrict__ eti) {
    int gt = blockIdx.x * blockDim.x + threadIdx.x;
    int i = gt >> 4;
    if (i >= NE) return;
    int c = (gt & 15) * 4;

    int s = __ldg(&src[i]);
    int d = __ldg(&dst[i]);
    int r = __ldg(&ety[i]);
    int t = __ldg(&eti[i]);
    float att = __ldg(&g_ex[i]) / __ldg(&g_den[d]);

    float4 xv = *(const float4*)(x   + (size_t)s * DD + c);
    float4 tv = *(const float4*)(tm  + (size_t)t * DD + c);
    float4 rv = *(const float4*)(rel + (size_t)r * DD + c);

    float4 o;
    o.x = (xv.x + tv.x) * (rv.x + tv.x) * att;
    o.y = (xv.y + tv.y) * (rv.y + tv.y) * att;
    o.z = (xv.z + tv.z) * (rv.z + tv.z) * att;
    o.w = (xv.w + tv.w) * (rv.w + tv.w) * att;

    float* p = &g_agg[(size_t)d * DD + c];
    asm volatile("red.global.add.v4.f32 [%0], {%1,%2,%3,%4};"
                 :: "l"(p), "f"(o.x), "f"(o.y), "f"(o.z), "f"(o.w)
                 : "memory");
}

// ---------------------------------------------------------------------------
// x_out = agg @ trans_w + x @ loop_w   (64-row tile, 4x4 register tiles)
// ---------------------------------------------------------------------------
__global__ void k_gemm(const float* __restrict__ x,
                       const float* __restrict__ wt,
                       const float* __restrict__ wl,
                       float* __restrict__ out) {
    __shared__ __align__(16) float sWt[DD * DD];
    __shared__ __align__(16) float sWl[DD * DD];
    __shared__ float sA[64 * 65];
    __shared__ float sX[64 * 65];

    int tid = threadIdx.x;
    for (int j = tid; j < DD * DD; j += 256) { sWt[j] = wt[j]; sWl[j] = wl[j]; }

    int row0 = blockIdx.x * 64;
    {
        int r = tid >> 4;
        int c4 = (tid & 15) * 4;
        for (int rr = r; rr < 64; rr += 16) {
            int grow = row0 + rr;
            float4 a = make_float4(0.f, 0.f, 0.f, 0.f);
            float4 b = make_float4(0.f, 0.f, 0.f, 0.f);
            if (grow < NN) {
                a = *(const float4*)&g_agg[(size_t)grow * DD + c4];
                b = *(const float4*)(x + (size_t)grow * DD + c4);
            }
            float* pa = &sA[rr * 65 + c4];
            float* pb = &sX[rr * 65 + c4];
            pa[0] = a.x; pa[1] = a.y; pa[2] = a.z; pa[3] = a.w;
            pb[0] = b.x; pb[1] = b.y; pb[2] = b.z; pb[3] = b.w;
        }
    }
    __syncthreads();

    int tx = tid & 15;   // column group (4 cols)
    int ty = tid >> 4;   // row group   (4 rows)
    float acc[4][4];
#pragma unroll
    for (int ri = 0; ri < 4; ri++)
#pragma unroll
        for (int cj = 0; cj < 4; cj++) acc[ri][cj] = 0.f;

#pragma unroll 4
    for (int k = 0; k < DD; k++) {
        float4 w0 = *(const float4*)&sWt[k * DD + tx * 4];
        float4 w1 = *(const float4*)&sWl[k * DD + tx * 4];
#pragma unroll
        for (int ri = 0; ri < 4; ri++) {
            float a = sA[(ty * 4 + ri) * 65 + k];
            float b = sX[(ty * 4 + ri) * 65 + k];
            acc[ri][0] += a * w0.x + b * w1.x;
            acc[ri][1] += a * w0.y + b * w1.y;
            acc[ri][2] += a * w0.z + b * w1.z;
            acc[ri][3] += a * w0.w + b * w1.w;
        }
    }

#pragma unroll
    for (int ri = 0; ri < 4; ri++) {
        int grow = row0 + ty * 4 + ri;
        if (grow < NN) {
            float4 v = make_float4(acc[ri][0], acc[ri][1], acc[ri][2], acc[ri][3]);
            *(float4*)(out + (size_t)grow * DD + tx * 4) = v;
        }
    }
}

// ---------------------------------------------------------------------------
// rel_out = rel_repr @ w_rel   (500x64 @ 64x64 — tiny)
// ---------------------------------------------------------------------------
__global__ void k_rel(const float* __restrict__ rel,
                      const float* __restrict__ wr,
                      float* __restrict__ out) {
    __shared__ float sR[4][DD];
    int tid = threadIdx.x;
    int j = tid & 63, ry = tid >> 6;
    int r0 = blockIdx.x * 4;
    int grow = r0 + ry;
    sR[ry][j] = (grow < NR) ? rel[(size_t)grow * DD + j] : 0.f;
    __syncthreads();
    float acc = 0.f;
#pragma unroll 8
    for (int k = 0; k < DD; k++) acc += sR[ry][k] * __ldg(&wr[k * DD + j]);
    if (grow < NR) out[(size_t)grow * DD + j] = acc;
}

// ---------------------------------------------------------------------------
extern "C" void kernel_launch(void* const* d_in, const int* in_sizes, int n_in,
                              void* d_out, int out_size) {
    const float* x       = (const float*)d_in[0];
    const float* rel     = (const float*)d_in[1];
    const float* tm      = (const float*)d_in[2];
    const int*   src     = (const int*)d_in[3];
    const int*   dst     = (const int*)d_in[4];
    const int*   ety     = (const int*)d_in[5];
    const int*   eti     = (const int*)d_in[6];
    const float* trans_w = (const float*)d_in[7];
    const float* loop_w  = (const float*)d_in[8];
    const float* w_rel   = (const float*)d_in[9];
    const float* ah      = (const float*)d_in[10];
    const float* at      = (const float*)d_in[11];
    const float* ar      = (const float*)d_in[12];
    const float* ats     = (const float*)d_in[13];

    float* out   = (float*)d_out;            // x_out  [50000*64]
    float* out_r = out + (size_t)NN * DD;    // rel_out [500*64]

    k_init<<<1024, 256>>>();

    {
        int warps = NN + NR + NT;
        int blocks = (warps * 32 + 255) / 256;
        k_scalar<<<blocks, 256>>>(x, rel, tm, ah, at, ar, ats);
    }

    k_edge1<<<(NE + 255) / 256, 256>>>(src, dst, ety, eti);

    {
        long long threads = (long long)NE * 16;
        int blocks = (int)((threads + 255) / 256);
        k_edge2<<<blocks, 256>>>(x, rel, tm, src, dst, ety, eti);
    }

    k_gemm<<<(NN + 63) / 64, 256>>>(x, trans_w, loop_w, out);
    k_rel<<<(NR + 3) / 4, 256>>>(rel, w_rel, out_r);

    (void)in_sizes; (void)n_in; (void)out_size;
}

// round 2
// speedup vs baseline: 1.6900x; 1.6900x over previous
#include <cuda_runtime.h>
#include <math.h>

#define NN 50000
#define NE 800000
#define DD 64
#define NR 500
#define NT 1000

// ---- scratch (no allocs allowed) ----
__device__ float g_ex[NE];
__device__ float g_att[NE];
__device__ float g_den[NN];
__device__ float g_agg[NN * DD];
__device__ float g_hatt[NN];
__device__ float g_tatt[NN];
__device__ float g_ratt[NR];
__device__ float g_tsatt[NT];
__device__ int4  g_pidx[NE];   // {src, dst, etype, etime}

// ---------------------------------------------------------------------------
// Prep: zero den + agg, pack the 4 index arrays into one int4 per edge.
// ---------------------------------------------------------------------------
__global__ void k_prep(const int* __restrict__ src, const int* __restrict__ dst,
                       const int* __restrict__ ety, const int* __restrict__ eti) {
    int i = blockIdx.x * blockDim.x + threadIdx.x;
    int stride = gridDim.x * blockDim.x;
    for (int j = i; j < NN * DD; j += stride) g_agg[j] = 0.f;
    for (int j = i; j < NN; j += stride) g_den[j] = 0.f;
    for (int j = i; j < NE; j += stride)
        g_pidx[j] = make_int4(src[j], dst[j], ety[j], eti[j]);
}

// ---------------------------------------------------------------------------
// Per-row scalar attention projections: warp per row.
// ---------------------------------------------------------------------------
__global__ void k_scalar(const float* __restrict__ x,
                         const float* __restrict__ rel,
                         const float* __restrict__ tm,
                         const float* __restrict__ ah,
                         const float* __restrict__ at,
                         const float* __restrict__ ar,
                         const float* __restrict__ ats) {
    int w = (blockIdx.x * blockDim.x + threadIdx.x) >> 5;
    int lane = threadIdx.x & 31;
    if (w < NN) {
        const float* row = x + (size_t)w * DD;
        float v0 = row[lane], v1 = row[lane + 32];
        float h = v0 * ah[lane] + v1 * ah[lane + 32];
        float t = v0 * at[lane] + v1 * at[lane + 32];
#pragma unroll
        for (int o = 16; o; o >>= 1) {
            h += __shfl_xor_sync(0xffffffffu, h, o);
            t += __shfl_xor_sync(0xffffffffu, t, o);
        }
        if (lane == 0) { g_hatt[w] = h; g_tatt[w] = t; }
    } else if (w < NN + NR) {
        int r = w - NN;
        const float* row = rel + (size_t)r * DD;
        float s = row[lane] * ar[lane] + row[lane + 32] * ar[lane + 32];
#pragma unroll
        for (int o = 16; o; o >>= 1) s += __shfl_xor_sync(0xffffffffu, s, o);
        if (lane == 0) g_ratt[r] = s;
    } else if (w < NN + NR + NT) {
        int t = w - NN - NR;
        const float* row = tm + (size_t)t * DD;
        float s = row[lane] * ats[lane] + row[lane + 32] * ats[lane + 32];
#pragma unroll
        for (int o = 16; o; o >>= 1) s += __shfl_xor_sync(0xffffffffu, s, o);
        if (lane == 0) g_tsatt[t] = s;
    }
}

// ---------------------------------------------------------------------------
// Edge pass 1: ex = exp(leaky_relu(logit)); den[dst] += ex
// ---------------------------------------------------------------------------
__global__ void k_edge1() {
    int i = blockIdx.x * blockDim.x + threadIdx.x;
    if (i >= NE) return;
    int4 p = __ldg(&g_pidx[i]);
    float e = g_hatt[p.x] - g_tatt[p.y] + g_ratt[p.z] + g_tsatt[p.w];
    e = (e > 0.f) ? e : 0.1f * e;
    float ex = __expf(e);
    g_ex[i] = ex;
    atomicAdd(&g_den[p.y], ex);
}

// ---------------------------------------------------------------------------
// att = ex / den[dst]  (one thread per edge: 800K divides instead of 12.8M)
// ---------------------------------------------------------------------------
__global__ void k_att(const int* __restrict__ dst) {
    int i = blockIdx.x * blockDim.x + threadIdx.x;
    if (i >= NE) return;
    g_att[i] = __fdividef(g_ex[i], g_den[dst[i]]);
}

// ---------------------------------------------------------------------------
// Edge pass 2 (dominant): 8 threads per edge, 2x float4 per thread.
// agg[dst] += att * (x[src]+time) * (rel+time)  via red.global.add.v4.f32
// ---------------------------------------------------------------------------
__global__ void k_edge2(const float* __restrict__ x,
                        const float* __restrict__ rel,
                        const float* __restrict__ tm) {
    int gt = blockIdx.x * blockDim.x + threadIdx.x;
    int i = gt >> 3;
    if (i >= NE) return;
    int c = (gt & 7) * 4;          // cols [c, c+4) and [c+32, c+36)

    int4 p = __ldg(&g_pidx[i]);    // broadcast across the 8-lane group
    float att = __ldg(&g_att[i]);  // broadcast

    const float* xr = x   + (size_t)p.x * DD;
    const float* rr = rel + (size_t)p.z * DD;
    const float* tr = tm  + (size_t)p.w * DD;

    float4 x0 = *(const float4*)(xr + c);
    float4 x1 = *(const float4*)(xr + c + 32);
    float4 t0 = *(const float4*)(tr + c);
    float4 t1 = *(const float4*)(tr + c + 32);
    float4 r0 = *(const float4*)(rr + c);
    float4 r1 = *(const float4*)(rr + c + 32);

    float4 o0, o1;
    o0.x = (x0.x + t0.x) * (r0.x + t0.x) * att;
    o0.y = (x0.y + t0.y) * (r0.y + t0.y) * att;
    o0.z = (x0.z + t0.z) * (r0.z + t0.z) * att;
    o0.w = (x0.w + t0.w) * (r0.w + t0.w) * att;
    o1.x = (x1.x + t1.x) * (r1.x + t1.x) * att;
    o1.y = (x1.y + t1.y) * (r1.y + t1.y) * att;
    o1.z = (x1.z + t1.z) * (r1.z + t1.z) * att;
    o1.w = (x1.w + t1.w) * (r1.w + t1.w) * att;

    float* pd = &g_agg[(size_t)p.y * DD + c];
    asm volatile("red.global.add.v4.f32 [%0], {%1,%2,%3,%4};"
                 :: "l"(pd), "f"(o0.x), "f"(o0.y), "f"(o0.z), "f"(o0.w)
                 : "memory");
    asm volatile("red.global.add.v4.f32 [%0], {%1,%2,%3,%4};"
                 :: "l"(pd + 32), "f"(o1.x), "f"(o1.y), "f"(o1.z), "f"(o1.w)
                 : "memory");
}

// ---------------------------------------------------------------------------
// x_out = agg @ trans_w + x @ loop_w   (64-row tile, 4x4 register tiles)
// ---------------------------------------------------------------------------
__global__ void k_gemm(const float* __restrict__ x,
                       const float* __restrict__ wt,
                       const float* __restrict__ wl,
                       float* __restrict__ out) {
    __shared__ __align__(16) float sWt[DD * DD];
    __shared__ __align__(16) float sWl[DD * DD];
    __shared__ float sA[64 * 65];
    __shared__ float sX[64 * 65];

    int tid = threadIdx.x;
    for (int j = tid; j < DD * DD; j += 256) { sWt[j] = wt[j]; sWl[j] = wl[j]; }

    int row0 = blockIdx.x * 64;
    {
        int r = tid >> 4;
        int c4 = (tid & 15) * 4;
        for (int rr = r; rr < 64; rr += 16) {
            int grow = row0 + rr;
            float4 a = make_float4(0.f, 0.f, 0.f, 0.f);
            float4 b = make_float4(0.f, 0.f, 0.f, 0.f);
            if (grow < NN) {
                a = *(const float4*)&g_agg[(size_t)grow * DD + c4];
                b = *(const float4*)(x + (size_t)grow * DD + c4);
            }
            float* pa = &sA[rr * 65 + c4];
            float* pb = &sX[rr * 65 + c4];
            pa[0] = a.x; pa[1] = a.y; pa[2] = a.z; pa[3] = a.w;
            pb[0] = b.x; pb[1] = b.y; pb[2] = b.z; pb[3] = b.w;
        }
    }
    __syncthreads();

    int tx = tid & 15;   // column group (4 cols)
    int ty = tid >> 4;   // row group   (4 rows)
    float acc[4][4];
#pragma unroll
    for (int ri = 0; ri < 4; ri++)
#pragma unroll
        for (int cj = 0; cj < 4; cj++) acc[ri][cj] = 0.f;

#pragma unroll 4
    for (int k = 0; k < DD; k++) {
        float4 w0 = *(const float4*)&sWt[k * DD + tx * 4];
        float4 w1 = *(const float4*)&sWl[k * DD + tx * 4];
#pragma unroll
        for (int ri = 0; ri < 4; ri++) {
            float a = sA[(ty * 4 + ri) * 65 + k];
            float b = sX[(ty * 4 + ri) * 65 + k];
            acc[ri][0] += a * w0.x + b * w1.x;
            acc[ri][1] += a * w0.y + b * w1.y;
            acc[ri][2] += a * w0.z + b * w1.z;
            acc[ri][3] += a * w0.w + b * w1.w;
        }
    }

#pragma unroll
    for (int ri = 0; ri < 4; ri++) {
        int grow = row0 + ty * 4 + ri;
        if (grow < NN) {
            float4 v = make_float4(acc[ri][0], acc[ri][1], acc[ri][2], acc[ri][3]);
            *(float4*)(out + (size_t)grow * DD + tx * 4) = v;
        }
    }
}

// ---------------------------------------------------------------------------
// rel_out = rel_repr @ w_rel   (500x64 @ 64x64 — tiny)
// ---------------------------------------------------------------------------
__global__ void k_rel(const float* __restrict__ rel,
                      const float* __restrict__ wr,
                      float* __restrict__ out) {
    __shared__ float sR[4][DD];
    int tid = threadIdx.x;
    int j = tid & 63, ry = tid >> 6;
    int r0 = blockIdx.x * 4;
    int grow = r0 + ry;
    sR[ry][j] = (grow < NR) ? rel[(size_t)grow * DD + j] : 0.f;
    __syncthreads();
    float acc = 0.f;
#pragma unroll 8
    for (int k = 0; k < DD; k++) acc += sR[ry][k] * __ldg(&wr[k * DD + j]);
    if (grow < NR) out[(size_t)grow * DD + j] = acc;
}

// ---------------------------------------------------------------------------
extern "C" void kernel_launch(void* const* d_in, const int* in_sizes, int n_in,
                              void* d_out, int out_size) {
    const float* x       = (const float*)d_in[0];
    const float* rel     = (const float*)d_in[1];
    const float* tm      = (const float*)d_in[2];
    const int*   src     = (const int*)d_in[3];
    const int*   dst     = (const int*)d_in[4];
    const int*   ety     = (const int*)d_in[5];
    const int*   eti     = (const int*)d_in[6];
    const float* trans_w = (const float*)d_in[7];
    const float* loop_w  = (const float*)d_in[8];
    const float* w_rel   = (const float*)d_in[9];
    const float* ah      = (const float*)d_in[10];
    const float* at      = (const float*)d_in[11];
    const float* ar      = (const float*)d_in[12];
    const float* ats     = (const float*)d_in[13];

    float* out   = (float*)d_out;            // x_out  [50000*64]
    float* out_r = out + (size_t)NN * DD;    // rel_out [500*64]

    k_prep<<<1024, 256>>>(src, dst, ety, eti);

    {
        int warps = NN + NR + NT;
        int blocks = (warps * 32 + 255) / 256;
        k_scalar<<<blocks, 256>>>(x, rel, tm, ah, at, ar, ats);
    }

    k_edge1<<<(NE + 255) / 256, 256>>>();
    k_att<<<(NE + 255) / 256, 256>>>(dst);

    {
        long long threads = (long long)NE * 8;
        int blocks = (int)((threads + 255) / 256);
        k_edge2<<<blocks, 256>>>(x, rel, tm);
    }

    k_gemm<<<(NN + 63) / 64, 256>>>(x, trans_w, loop_w, out);
    k_rel<<<(NR + 3) / 4, 256>>>(rel, w_rel, out_r);

    (void)in_sizes; (void)n_in; (void)out_size;
}

// round 3
// speedup vs baseline: 1.7865x; 1.0571x over previous
#include <cuda_runtime.h>
#include <math.h>

#define NN 50000
#define NE 800000
#define DD 64
#define NR 500
#define NT 1000

// ---- scratch (no allocs allowed) ----
__device__ float g_ex[NE];
__device__ float g_den[NN];
__device__ float g_agg[NN * DD];
__device__ float g_hatt[NN];
__device__ float g_tatt[NN];
__device__ float g_ratt[NR];
__device__ float g_tsatt[NT];
__device__ int4  g_pidx[NE];   // {src, dst, etype, etime}

// ---------------------------------------------------------------------------
// Prep: zero den + agg only.
// ---------------------------------------------------------------------------
__global__ void k_prep() {
    int i = blockIdx.x * blockDim.x + threadIdx.x;
    int stride = gridDim.x * blockDim.x;
    for (int j = i; j < NN * DD; j += stride) g_agg[j] = 0.f;
    for (int j = i; j < NN; j += stride) g_den[j] = 0.f;
}

// ---------------------------------------------------------------------------
// Per-row scalar attention projections: warp per row.
// ---------------------------------------------------------------------------
__global__ void k_scalar(const float* __restrict__ x,
                         const float* __restrict__ rel,
                         const float* __restrict__ tm,
                         const float* __restrict__ ah,
                         const float* __restrict__ at,
                         const float* __restrict__ ar,
                         const float* __restrict__ ats) {
    int w = (blockIdx.x * blockDim.x + threadIdx.x) >> 5;
    int lane = threadIdx.x & 31;
    if (w < NN) {
        const float* row = x + (size_t)w * DD;
        float v0 = row[lane], v1 = row[lane + 32];
        float h = v0 * ah[lane] + v1 * ah[lane + 32];
        float t = v0 * at[lane] + v1 * at[lane + 32];
#pragma unroll
        for (int o = 16; o; o >>= 1) {
            h += __shfl_xor_sync(0xffffffffu, h, o);
            t += __shfl_xor_sync(0xffffffffu, t, o);
        }
        if (lane == 0) { g_hatt[w] = h; g_tatt[w] = t; }
    } else if (w < NN + NR) {
        int r = w - NN;
        const float* row = rel + (size_t)r * DD;
        float s = row[lane] * ar[lane] + row[lane + 32] * ar[lane + 32];
#pragma unroll
        for (int o = 16; o; o >>= 1) s += __shfl_xor_sync(0xffffffffu, s, o);
        if (lane == 0) g_ratt[r] = s;
    } else if (w < NN + NR + NT) {
        int t = w - NN - NR;
        const float* row = tm + (size_t)t * DD;
        float s = row[lane] * ats[lane] + row[lane + 32] * ats[lane + 32];
#pragma unroll
        for (int o = 16; o; o >>= 1) s += __shfl_xor_sync(0xffffffffu, s, o);
        if (lane == 0) g_tsatt[t] = s;
    }
}

// ---------------------------------------------------------------------------
// Edge pass 1: ex = exp(leaky_relu(logit)); den[dst] += ex.
// Also packs the 4 index arrays into g_pidx for edge2 (saves a prep pass).
// ---------------------------------------------------------------------------
__global__ void k_edge1(const int* __restrict__ src, const int* __restrict__ dst,
                        const int* __restrict__ ety, const int* __restrict__ eti) {
    int i = blockIdx.x * blockDim.x + threadIdx.x;
    if (i >= NE) return;
    int s = src[i], d = dst[i], r = ety[i], t = eti[i];
    g_pidx[i] = make_int4(s, d, r, t);
    float e = g_hatt[s] - g_tatt[d] + g_ratt[r] + g_tsatt[t];
    e = (e > 0.f) ? e : 0.1f * e;
    float ex = __expf(e);
    g_ex[i] = ex;
    atomicAdd(&g_den[d], ex);
}

// ---------------------------------------------------------------------------
// Edge pass 2 (dominant): 8 threads per edge, 2x float4 per thread.
// att computed once per edge (group leader) and shuffle-broadcast.
// agg[dst] += att * (x[src]+time) * (rel+time)  via red.global.add.v4.f32
// ---------------------------------------------------------------------------
__global__ void k_edge2(const float* __restrict__ x,
                        const float* __restrict__ rel,
                        const float* __restrict__ tm) {
    int gt = blockIdx.x * blockDim.x + threadIdx.x;
    int i = gt >> 3;
    if (i >= NE) return;
    int sub = gt & 7;
    int c = sub * 4;               // cols [c, c+4) and [c+32, c+36)

    int4 p = __ldg(&g_pidx[i]);    // broadcast across the 8-lane group

    // one divide per edge, broadcast to the group
    float att = 0.f;
    if (sub == 0) att = __fdividef(__ldg(&g_ex[i]), __ldg(&g_den[p.y]));
    att = __shfl_sync(0xffffffffu, att, (threadIdx.x & 31) & ~7);

    const float* xr = x   + (size_t)p.x * DD;
    const float* rr = rel + (size_t)p.z * DD;
    const float* tr = tm  + (size_t)p.w * DD;

    float4 x0 = *(const float4*)(xr + c);
    float4 x1 = *(const float4*)(xr + c + 32);
    float4 t0 = *(const float4*)(tr + c);
    float4 t1 = *(const float4*)(tr + c + 32);
    float4 r0 = *(const float4*)(rr + c);
    float4 r1 = *(const float4*)(rr + c + 32);

    float4 o0, o1;
    o0.x = (x0.x + t0.x) * (r0.x + t0.x) * att;
    o0.y = (x0.y + t0.y) * (r0.y + t0.y) * att;
    o0.z = (x0.z + t0.z) * (r0.z + t0.z) * att;
    o0.w = (x0.w + t0.w) * (r0.w + t0.w) * att;
    o1.x = (x1.x + t1.x) * (r1.x + t1.x) * att;
    o1.y = (x1.y + t1.y) * (r1.y + t1.y) * att;
    o1.z = (x1.z + t1.z) * (r1.z + t1.z) * att;
    o1.w = (x1.w + t1.w) * (r1.w + t1.w) * att;

    float* pd = &g_agg[(size_t)p.y * DD + c];
    asm volatile("red.global.add.v4.f32 [%0], {%1,%2,%3,%4};"
                 :: "l"(pd), "f"(o0.x), "f"(o0.y), "f"(o0.z), "f"(o0.w)
                 : "memory");
    asm volatile("red.global.add.v4.f32 [%0], {%1,%2,%3,%4};"
                 :: "l"(pd + 32), "f"(o1.x), "f"(o1.y), "f"(o1.z), "f"(o1.w)
                 : "memory");
}

// ---------------------------------------------------------------------------
// x_out = agg @ trans_w + x @ loop_w   (64-row tile, 4x4 register tiles)
// ---------------------------------------------------------------------------
__global__ void k_gemm(const float* __restrict__ x,
                       const float* __restrict__ wt,
                       const float* __restrict__ wl,
                       float* __restrict__ out) {
    __shared__ __align__(16) float sWt[DD * DD];
    __shared__ __align__(16) float sWl[DD * DD];
    __shared__ float sA[64 * 65];
    __shared__ float sX[64 * 65];

    int tid = threadIdx.x;
    for (int j = tid; j < DD * DD; j += 256) { sWt[j] = wt[j]; sWl[j] = wl[j]; }

    int row0 = blockIdx.x * 64;
    {
        int r = tid >> 4;
        int c4 = (tid & 15) * 4;
        for (int rr = r; rr < 64; rr += 16) {
            int grow = row0 + rr;
            float4 a = make_float4(0.f, 0.f, 0.f, 0.f);
            float4 b = make_float4(0.f, 0.f, 0.f, 0.f);
            if (grow < NN) {
                a = *(const float4*)&g_agg[(size_t)grow * DD + c4];
                b = *(const float4*)(x + (size_t)grow * DD + c4);
            }
            float* pa = &sA[rr * 65 + c4];
            float* pb = &sX[rr * 65 + c4];
            pa[0] = a.x; pa[1] = a.y; pa[2] = a.z; pa[3] = a.w;
            pb[0] = b.x; pb[1] = b.y; pb[2] = b.z; pb[3] = b.w;
        }
    }
    __syncthreads();

    int tx = tid & 15;   // column group (4 cols)
    int ty = tid >> 4;   // row group   (4 rows)
    float acc[4][4];
#pragma unroll
    for (int ri = 0; ri < 4; ri++)
#pragma unroll
        for (int cj = 0; cj < 4; cj++) acc[ri][cj] = 0.f;

#pragma unroll 4
    for (int k = 0; k < DD; k++) {
        float4 w0 = *(const float4*)&sWt[k * DD + tx * 4];
        float4 w1 = *(const float4*)&sWl[k * DD + tx * 4];
#pragma unroll
        for (int ri = 0; ri < 4; ri++) {
            float a = sA[(ty * 4 + ri) * 65 + k];
            float b = sX[(ty * 4 + ri) * 65 + k];
            acc[ri][0] += a * w0.x + b * w1.x;
            acc[ri][1] += a * w0.y + b * w1.y;
            acc[ri][2] += a * w0.z + b * w1.z;
            acc[ri][3] += a * w0.w + b * w1.w;
        }
    }

#pragma unroll
    for (int ri = 0; ri < 4; ri++) {
        int grow = row0 + ty * 4 + ri;
        if (grow < NN) {
            float4 v = make_float4(acc[ri][0], acc[ri][1], acc[ri][2], acc[ri][3]);
            *(float4*)(out + (size_t)grow * DD + tx * 4) = v;
        }
    }
}

// ---------------------------------------------------------------------------
// rel_out = rel_repr @ w_rel   (500x64 @ 64x64 — tiny)
// ---------------------------------------------------------------------------
__global__ void k_rel(const float* __restrict__ rel,
                      const float* __restrict__ wr,
                      float* __restrict__ out) {
    __shared__ float sR[4][DD];
    int tid = threadIdx.x;
    int j = tid & 63, ry = tid >> 6;
    int r0 = blockIdx.x * 4;
    int grow = r0 + ry;
    sR[ry][j] = (grow < NR) ? rel[(size_t)grow * DD + j] : 0.f;
    __syncthreads();
    float acc = 0.f;
#pragma unroll 8
    for (int k = 0; k < DD; k++) acc += sR[ry][k] * __ldg(&wr[k * DD + j]);
    if (grow < NR) out[(size_t)grow * DD + j] = acc;
}

// ---------------------------------------------------------------------------
extern "C" void kernel_launch(void* const* d_in, const int* in_sizes, int n_in,
                              void* d_out, int out_size) {
    const float* x       = (const float*)d_in[0];
    const float* rel     = (const float*)d_in[1];
    const float* tm      = (const float*)d_in[2];
    const int*   src     = (const int*)d_in[3];
    const int*   dst     = (const int*)d_in[4];
    const int*   ety     = (const int*)d_in[5];
    const int*   eti     = (const int*)d_in[6];
    const float* trans_w = (const float*)d_in[7];
    const float* loop_w  = (const float*)d_in[8];
    const float* w_rel   = (const float*)d_in[9];
    const float* ah      = (const float*)d_in[10];
    const float* at      = (const float*)d_in[11];
    const float* ar      = (const float*)d_in[12];
    const float* ats     = (const float*)d_in[13];

    float* out   = (float*)d_out;            // x_out  [50000*64]
    float* out_r = out + (size_t)NN * DD;    // rel_out [500*64]

    k_prep<<<1024, 256>>>();

    {
        int warps = NN + NR + NT;
        int blocks = (warps * 32 + 255) / 256;
        k_scalar<<<blocks, 256>>>(x, rel, tm, ah, at, ar, ats);
    }

    k_edge1<<<(NE + 255) / 256, 256>>>(src, dst, ety, eti);

    {
        long long threads = (long long)NE * 8;
        int blocks = (int)((threads + 255) / 256);
        k_edge2<<<blocks, 256>>>(x, rel, tm);
    }

    k_gemm<<<(NN + 63) / 64, 256>>>(x, trans_w, loop_w, out);
    k_rel<<<(NR + 3) / 4, 256>>>(rel, w_rel, out_r);

    (void)in_sizes; (void)n_in; (void)out_size;
}